// round 16
// baseline (speedup 1.0000x reference)
#include <cuda_runtime.h>
#include <cuda_fp16.h>
#include <math.h>

// Problem constants (validated against in_sizes at launch)
#define NMAX 100000
#define NPAD 100128           // NMAX rounded up past 128-row tile
#define EMAX 3200000
#define ND   128
#define INDIM 48

// ---------------- scratch (device globals; no allocation allowed) ----------------
__device__ __align__(16) __half g_y[(size_t)NPAD * ND];    // x @ W (fp16), gathered by SpMM
__device__ __align__(16) __half g_xh[(size_t)NPAD * ND];   // fp16 residual stream x
__device__ __align__(16) __half g_nfh[(size_t)NPAD * INDIM]; // fp16 copy of node_features
__device__ __align__(16) uint2  g_wpack[1536 + 3 * 4096];  // W in mma-B-fragment order
__device__ double g_degp[NMAX];             // packed (count*2^32 + valsum); zeroed by scanA
__device__ float g_dinv[NMAX];
__device__ int   g_rowptr[NMAX + 1];
__device__ int   g_fill[NMAX];              // set to count by scanA, counted down by scatter -> 0
__device__ __align__(8) int2 g_ecw[EMAX];   // CSR: (col, weight bits) interleaved
__device__ int   g_bsum[64];                // per-tile totals (raw)

// ---------------- small helpers ----------------
__device__ __forceinline__ void fma4(float4& d, float a, const float4& w) {
    d.x += a * w.x; d.y += a * w.y; d.z += a * w.z; d.w += a * w.w;
}
__device__ __forceinline__ float4 h4_to_f4(uint2 u) {
    __half2 a = *(__half2*)&u.x;
    __half2 b = *(__half2*)&u.y;
    float2 fa = __half22float2(a);
    float2 fb = __half22float2(b);
    return make_float4(fa.x, fa.y, fb.x, fb.y);
}
__device__ __forceinline__ unsigned pack_h2(float a, float b) {
    __half2 h = __floats2half2_rn(a, b);
    return *(unsigned*)&h;
}
__device__ __forceinline__ void mma16816(float4& c, unsigned a0, unsigned a1, unsigned a2,
                                         unsigned a3, unsigned b0, unsigned b1) {
    asm volatile(
        "mma.sync.aligned.m16n8k16.row.col.f32.f16.f16.f32 "
        "{%0,%1,%2,%3}, {%4,%5,%6,%7}, {%8,%9}, {%0,%1,%2,%3};\n"
        : "+f"(c.x), "+f"(c.y), "+f"(c.z), "+f"(c.w)
        : "r"(a0), "r"(a1), "r"(a2), "r"(a3), "r"(b0), "r"(b1));
}

// ---------------- graph preprocessing ----------------
// 1) ONE packed atomic per edge: low part accumulates vals, 2^32 part counts edges
__global__ void k_edge_deg(const int* __restrict__ row, const float* __restrict__ vals, int e) {
    int i = blockIdx.x * blockDim.x + threadIdx.x;
    if (i < e) {
        int r = __ldg(&row[i]);
        atomicAdd(&g_degp[r], (double)__ldg(&vals[i]) + 4294967296.0);
    }
}

// 2) unpack counts+valsums; tile-local scan of counts -> g_rowptr; dinv; store count
//    to g_fill (scatter cursor); re-zero g_degp (invariant for next replay)
__global__ void k_scanA(int n) {
    __shared__ int wsum[32];
    int t = threadIdx.x;
    int base = blockIdx.x * 4096;
    int v[4]; int sum = 0;
#pragma unroll
    for (int k = 0; k < 4; k++) {
        int idx = base + t * 4 + k;
        int c = 0;
        if (idx < n) {
            double d = g_degp[idx];
            c = (int)(d * 2.3283064365386963e-10);      // d * 2^-32 (floor; exact here)
            double valsum = d - (double)c * 4294967296.0;
            g_dinv[idx] = rsqrtf(fmaxf((float)valsum + 1.0f, 1.0f));   // +1 self-loop
            g_degp[idx] = 0.0;                           // restore zero-invariant
            g_fill[idx] = c;                             // scatter countdown cursor
        }
        v[k] = c;
        sum += c;
    }
    int lane = t & 31, wid = t >> 5;
    int inc = sum;
#pragma unroll
    for (int off = 1; off < 32; off <<= 1) {
        int q = __shfl_up_sync(0xffffffff, inc, off);
        if (lane >= off) inc += q;
    }
    if (lane == 31) wsum[wid] = inc;
    __syncthreads();
    if (wid == 0) {
        int w = wsum[lane];
#pragma unroll
        for (int off = 1; off < 32; off <<= 1) {
            int q = __shfl_up_sync(0xffffffff, w, off);
            if (lane >= off) w += q;
        }
        wsum[lane] = w;
    }
    __syncthreads();
    int excl = inc - sum + (wid > 0 ? wsum[wid - 1] : 0);
    if (t == 1023) g_bsum[blockIdx.x] = excl + sum;   // raw tile total
    int run = excl;
#pragma unroll
    for (int k = 0; k < 4; k++) {
        int idx = base + t * 4 + k;
        if (idx < n) g_rowptr[idx] = run;
        run += v[k];
    }
}

// 3) add cross-tile prefix (each 256-thread block spans exactly one 4096-tile)
__global__ void k_scanC(int n, int e) {
    __shared__ int pref;
    int tile = (int)(blockIdx.x >> 4);      // blockIdx.x*256 / 4096
    if (threadIdx.x < 32) {
        int v = ((int)threadIdx.x < tile) ? g_bsum[threadIdx.x] : 0;
#pragma unroll
        for (int off = 16; off > 0; off >>= 1)
            v += __shfl_down_sync(0xffffffff, v, off);
        if (threadIdx.x == 0) pref = v;
    }
    __syncthreads();
    int i = blockIdx.x * blockDim.x + threadIdx.x;
    if (i < n) g_rowptr[i] += pref;
    if (i == 0) g_rowptr[n] = e;
}

// 4) scatter normalized (col, weight); countdown cursor leaves g_fill at 0
__global__ void k_scatter(const int* __restrict__ row, const int* __restrict__ col,
                          const float* __restrict__ vals, int e) {
    int i = blockIdx.x * blockDim.x + threadIdx.x;
    if (i < e) {
        int r = __ldg(&row[i]), c = __ldg(&col[i]);
        int pos = g_rowptr[r] + atomicSub(&g_fill[r], 1) - 1;
        float w = __ldg(&vals[i]) * g_dinv[r] * g_dinv[c];
        g_ecw[pos] = make_int2(c, __float_as_int(w));
    }
}

// ---------------- weight repack + node_features fp16 conversion (fused) ----------------
__global__ void k_prep(const float* __restrict__ Win, const float* __restrict__ Wc,
                       const float* __restrict__ nf, int L, int wtot, int cnt4) {
    int t = blockIdx.x * blockDim.x + threadIdx.x;
    if (t < wtot) {
        const float* W;
        int idx;
        if (t < 1536) { W = Win; idx = t; }
        else {
            int l = (t - 1536) >> 12;
            idx = (t - 1536) & 4095;
            W = Wc + (size_t)l * ND * ND;
        }
        int kc   = idx >> 9;
        int rest = idx & 511;
        int nt   = rest >> 5;
        int lane = rest & 31;
        int n  = nt * 8 + (lane >> 2);
        int k0 = kc * 16 + (lane & 3) * 2;
        uint2 p;
        p.x = pack_h2(W[(size_t)k0 * ND + n],       W[(size_t)(k0 + 1) * ND + n]);
        p.y = pack_h2(W[(size_t)(k0 + 8) * ND + n], W[(size_t)(k0 + 9) * ND + n]);
        g_wpack[t] = p;
    } else {
        int i = t - wtot;
        if (i < cnt4) {
            float4 v = ((const float4*)nf)[i];
            uint2 p;
            p.x = pack_h2(v.x, v.y);
            p.y = pack_h2(v.z, v.w);
            ((uint2*)g_nfh)[i] = p;
        }
    }
}

// ---------------- tensor-core GEMM ----------------
// Block: 64 rows x 128 cols, 256 threads (8 warps). Warp: rg = w/2, col-half h = w%2.
// MODE 0: out = relu(acc + bias) -> g_xh fp16 ONLY (input projection; no fp32 write)
// MODE 1: out = acc -> g_y fp16 (layer pre-aggregation)
template<int KC, int MODE, int ASEL>
__global__ void __launch_bounds__(256)
k_mma(int wofs, const float* __restrict__ bias, int n) {
    const int AS = KC * 16;
    const __half* A = (ASEL == 0) ? g_nfh : g_xh;
    int tid = threadIdx.x;
    int warp = tid >> 5, lane = tid & 31;
    int rg = warp >> 1, h = warp & 1;
    int g = lane >> 2, tq = lane & 3;
    int row0 = blockIdx.x * 64 + rg * 16;

    float4 acc[8];
#pragma unroll
    for (int nt = 0; nt < 8; nt++) acc[nt] = make_float4(0.f, 0.f, 0.f, 0.f);

    const __half* ar0 = A + (size_t)(row0 + g) * AS;
    const __half* ar8 = A + (size_t)(row0 + g + 8) * AS;
    const uint2* wp = g_wpack + wofs + h * 256 + lane;

#pragma unroll
    for (int kc = 0; kc < KC; kc++) {
        int k0 = kc * 16 + tq * 2;
        unsigned a0 = *(const unsigned*)(ar0 + k0);
        unsigned a1 = *(const unsigned*)(ar8 + k0);
        unsigned a2 = *(const unsigned*)(ar0 + k0 + 8);
        unsigned a3 = *(const unsigned*)(ar8 + k0 + 8);
        const uint2* w = wp + kc * 512;
#pragma unroll
        for (int nt = 0; nt < 8; nt++) {
            uint2 b = __ldg(&w[nt * 32]);
            mma16816(acc[nt], a0, a1, a2, a3, b.x, b.y);
        }
    }

    int r0 = row0 + g;
    int r1 = row0 + g + 8;
    bool ok0 = r0 < n, ok1 = r1 < n;
    int colb = h * 64 + tq * 2;

    if (MODE == 1) {
        __half* y0 = g_y + (size_t)r0 * ND + colb;
        __half* y1 = g_y + (size_t)r1 * ND + colb;
#pragma unroll
        for (int nt = 0; nt < 8; nt++) {
            unsigned h01 = pack_h2(acc[nt].x, acc[nt].y);
            unsigned h23 = pack_h2(acc[nt].z, acc[nt].w);
            if (ok0) *(unsigned*)(y0 + nt * 8) = h01;
            if (ok1) *(unsigned*)(y1 + nt * 8) = h23;
        }
    } else {
        __half* xh0 = g_xh + (size_t)r0 * ND + colb;
        __half* xh1 = g_xh + (size_t)r1 * ND + colb;
#pragma unroll
        for (int nt = 0; nt < 8; nt++) {
            float2 bb = __ldg(&((const float2*)bias)[h * 32 + nt * 4 + tq]);
            float v0 = fmaxf(acc[nt].x + bb.x, 0.f);
            float v1 = fmaxf(acc[nt].y + bb.y, 0.f);
            float v2 = fmaxf(acc[nt].z + bb.x, 0.f);
            float v3 = fmaxf(acc[nt].w + bb.y, 0.f);
            if (ok0) *(unsigned*)(xh0 + nt * 8) = pack_h2(v0, v1);
            if (ok1) *(unsigned*)(xh1 + nt * 8) = pack_h2(v2, v3);
        }
    }
}

// ---------------- SpMM (fp16 gather) + bias + ReLU + residual, fused ----------------
// x[w,:] = xh[w,:] + relu( sum_j ew[j]*y[col[j],:] + dinv[w]^2*y[w,:] + b )
// Residual stream lives in fp16 g_xh; last layer writes fp32 output instead.
__global__ void k_spmm_fused(float* __restrict__ xout, const float* __restrict__ b, int n,
                             int last) {
    int gt = blockIdx.x * blockDim.x + threadIdx.x;
    int w = gt >> 5;
    int lane = gt & 31;
    if (w >= n) return;
    const uint2* y2 = (const uint2*)g_y;        // 4 halfs per lane
    float di = g_dinv[w];
    float s = di * di;                          // self-loop weight
    float4 v = h4_to_f4(__ldg(&y2[(size_t)w * 32 + lane]));
    float4 acc = make_float4(s * v.x, s * v.y, s * v.z, s * v.w);
    int jb = g_rowptr[w], je = g_rowptr[w + 1];
    int j = jb;
    for (; j + 8 <= je; j += 8) {
        int2 e[8];
        uint2 u[8];
#pragma unroll
        for (int q = 0; q < 8; q++) e[q] = __ldg(&g_ecw[j + q]);
#pragma unroll
        for (int q = 0; q < 8; q++) u[q] = __ldg(&y2[(size_t)e[q].x * 32 + lane]);
#pragma unroll
        for (int q = 0; q < 8; q++) fma4(acc, __int_as_float(e[q].y), h4_to_f4(u[q]));
    }
    if (j + 4 <= je) {
        int2 e[4];
        uint2 u[4];
#pragma unroll
        for (int q = 0; q < 4; q++) e[q] = __ldg(&g_ecw[j + q]);
#pragma unroll
        for (int q = 0; q < 4; q++) u[q] = __ldg(&y2[(size_t)e[q].x * 32 + lane]);
#pragma unroll
        for (int q = 0; q < 4; q++) fma4(acc, __int_as_float(e[q].y), h4_to_f4(u[q]));
        j += 4;
    }
    for (; j < je; j++) {
        int2 e = __ldg(&g_ecw[j]);
        fma4(acc, __int_as_float(e.y), h4_to_f4(__ldg(&y2[(size_t)e.x * 32 + lane])));
    }
    float4 bb = __ldg(&((const float4*)b)[lane]);
    uint2* xh2 = (uint2*)g_xh;
    float4 xv = h4_to_f4(xh2[(size_t)w * 32 + lane]);   // fp16 residual read
    xv.x += fmaxf(acc.x + bb.x, 0.f);
    xv.y += fmaxf(acc.y + bb.y, 0.f);
    xv.z += fmaxf(acc.z + bb.z, 0.f);
    xv.w += fmaxf(acc.w + bb.w, 0.f);
    if (last) {
        ((float4*)xout)[(size_t)w * 32 + lane] = xv;    // final fp32 output
    } else {
        uint2 p;
        p.x = pack_h2(xv.x, xv.y);
        p.y = pack_h2(xv.z, xv.w);
        xh2[(size_t)w * 32 + lane] = p;                 // fp16 residual write
    }
}

// ---------------- launch ----------------
extern "C" void kernel_launch(void* const* d_in, const int* in_sizes, int n_in,
                              void* d_out, int out_size) {
    const float* nf    = (const float*)d_in[0];   // [N,48]
    const int*   erow  = (const int*)d_in[1];     // [E]
    const int*   ecol  = (const int*)d_in[2];     // [E]
    const float* evals = (const float*)d_in[3];   // [E]
    const float* Win   = (const float*)d_in[4];   // [48,128]
    const float* bin   = (const float*)d_in[5];   // [128]
    const float* Wc    = (const float*)d_in[6];   // [L,128,128]
    const float* bc    = (const float*)d_in[7];   // [L,128]

    int N = in_sizes[0] / INDIM;
    int E = in_sizes[1];
    int L = in_sizes[6] / (ND * ND);
    if (N > NMAX) N = NMAX;
    if (E > EMAX) E = EMAX;
    if (L > 3) L = 3;
    if (L < 1) L = 1;

    float* x = (float*)d_out;

    int spmm_blocks = (N * 32 + 255) / 256;
    int gblocks = (N + 63) / 64;
    int nb = (N + 4095) / 4096;
    int wtot = 1536 + L * 4096;
    int cnt4 = N * INDIM / 4;

    // Fork a secondary stream for the dense prologue (prep + input proj + layer-0 y),
    // which is independent of the CSR build. Host-side objects only (no device alloc).
    cudaStream_t s2 = 0;
    cudaEvent_t evFork = 0, evJoin = 0;
    bool forked = false;
    if (cudaStreamCreateWithFlags(&s2, cudaStreamNonBlocking) == cudaSuccess) {
        if (cudaEventCreateWithFlags(&evFork, cudaEventDisableTiming) == cudaSuccess &&
            cudaEventCreateWithFlags(&evJoin, cudaEventDisableTiming) == cudaSuccess) {
            forked = true;
        }
    }

    if (forked) {
        cudaEventRecord(evFork, 0);
        cudaStreamWaitEvent(s2, evFork, 0);
    }
    cudaStream_t sb = forked ? s2 : 0;   // dense branch stream

    // dense branch: wpack/nfh -> input projection (xh fp16) -> layer-0 y = x @ Wc[0]
    k_prep<<<(wtot + cnt4 + 255) / 256, 256, 0, sb>>>(Win, Wc, nf, L, wtot, cnt4);
    k_mma<3, 0, 0><<<gblocks, 256, 0, sb>>>(0, bin, N);
    k_mma<8, 1, 1><<<gblocks, 256, 0, sb>>>(1536, nullptr, N);

    // CSR branch (default stream): rebuild graph structure + normalization
    k_edge_deg<<<(E + 255) / 256, 256>>>(erow, evals, E);
    k_scanA<<<nb, 1024>>>(N);
    k_scanC<<<(N + 255) / 256, 256>>>(N, E);
    k_scatter<<<(E + 255) / 256, 256>>>(erow, ecol, evals, E);

    if (forked) {
        cudaEventRecord(evJoin, s2);
        cudaStreamWaitEvent(0, evJoin, 0);
    }

    // layer 0 aggregation, then remaining layers (last one writes fp32 output)
    k_spmm_fused<<<spmm_blocks, 256>>>(x, bc, N, L == 1);
    for (int l = 1; l < L; l++) {
        k_mma<8, 1, 1><<<gblocks, 256>>>(1536 + l * 4096, nullptr, N);
        k_spmm_fused<<<spmm_blocks, 256>>>(x, bc + (size_t)l * ND, N, l == L - 1);
    }
}

// round 17
// speedup vs baseline: 1.0203x; 1.0203x over previous
#include <cuda_runtime.h>
#include <cuda_fp16.h>
#include <math.h>

// Problem constants (validated against in_sizes at launch)
#define NMAX 100000
#define NPAD 100128           // NMAX rounded up past 128-row tile
#define EMAX 3200000
#define ND   128
#define INDIM 48

// ---------------- scratch (device globals; no allocation allowed) ----------------
__device__ __align__(16) __half g_y[(size_t)NPAD * ND];    // x @ W (fp16), gathered by SpMM
__device__ __align__(16) __half g_xh[(size_t)NPAD * ND];   // fp16 copy of x (GEMM A operand)
__device__ __align__(16) __half g_nfh[(size_t)NPAD * INDIM]; // fp16 copy of node_features
__device__ __align__(16) uint2  g_wpack[1536 + 3 * 4096];  // W in mma-B-fragment order
__device__ double g_degp[NMAX];             // packed (count*2^32 + valsum); zeroed by scanA
__device__ float g_dinv[NMAX];
__device__ int   g_rowptr[NMAX + 1];        // tile-local offsets (finalized via g_bsum prefix)
__device__ int   g_fill[NMAX];              // set to count by scanA, counted down by scatter -> 0
__device__ __align__(8) int2 g_ecw[EMAX];   // CSR: (col, weight bits) interleaved
__device__ int   g_bsum[64];                // tile totals -> exclusive prefixes (last block)
__device__ int   g_ticket;                  // scanA last-block ticket; reset to 0 each pass

// ---------------- small helpers ----------------
__device__ __forceinline__ void fma4(float4& d, float a, const float4& w) {
    d.x += a * w.x; d.y += a * w.y; d.z += a * w.z; d.w += a * w.w;
}
__device__ __forceinline__ float4 h4_to_f4(uint2 u) {
    __half2 a = *(__half2*)&u.x;
    __half2 b = *(__half2*)&u.y;
    float2 fa = __half22float2(a);
    float2 fb = __half22float2(b);
    return make_float4(fa.x, fa.y, fb.x, fb.y);
}
__device__ __forceinline__ unsigned pack_h2(float a, float b) {
    __half2 h = __floats2half2_rn(a, b);
    return *(unsigned*)&h;
}
__device__ __forceinline__ void mma16816(float4& c, unsigned a0, unsigned a1, unsigned a2,
                                         unsigned a3, unsigned b0, unsigned b1) {
    asm volatile(
        "mma.sync.aligned.m16n8k16.row.col.f32.f16.f16.f32 "
        "{%0,%1,%2,%3}, {%4,%5,%6,%7}, {%8,%9}, {%0,%1,%2,%3};\n"
        : "+f"(c.x), "+f"(c.y), "+f"(c.z), "+f"(c.w)
        : "r"(a0), "r"(a1), "r"(a2), "r"(a3), "r"(b0), "r"(b1));
}

// ---------------- graph preprocessing ----------------
// 1) ONE packed atomic per edge: low part accumulates vals, 2^32 part counts edges
__global__ void k_edge_deg(const int* __restrict__ row, const float* __restrict__ vals, int e) {
    int i = blockIdx.x * blockDim.x + threadIdx.x;
    if (i < e) {
        int r = __ldg(&row[i]);
        atomicAdd(&g_degp[r], (double)__ldg(&vals[i]) + 4294967296.0);
    }
}

// 2) unpack counts+valsums; tile-local scan of counts -> g_rowptr; dinv; store count
//    to g_fill (scatter cursor); re-zero g_degp. The LAST block (atomic ticket) then
//    converts g_bsum tile totals into exclusive prefixes in place and resets the ticket.
__global__ void k_scanA(int n) {
    __shared__ int wsum[32];
    __shared__ int is_last;
    int t = threadIdx.x;
    int base = blockIdx.x * 4096;
    int v[4]; int sum = 0;
#pragma unroll
    for (int k = 0; k < 4; k++) {
        int idx = base + t * 4 + k;
        int c = 0;
        if (idx < n) {
            double d = g_degp[idx];
            c = (int)(d * 2.3283064365386963e-10);      // d * 2^-32 (floor; exact here)
            double valsum = d - (double)c * 4294967296.0;
            g_dinv[idx] = rsqrtf(fmaxf((float)valsum + 1.0f, 1.0f));   // +1 self-loop
            g_degp[idx] = 0.0;                           // restore zero-invariant
            g_fill[idx] = c;                             // scatter countdown cursor
        }
        v[k] = c;
        sum += c;
    }
    int lane = t & 31, wid = t >> 5;
    int inc = sum;
#pragma unroll
    for (int off = 1; off < 32; off <<= 1) {
        int q = __shfl_up_sync(0xffffffff, inc, off);
        if (lane >= off) inc += q;
    }
    if (lane == 31) wsum[wid] = inc;
    __syncthreads();
    if (wid == 0) {
        int w = wsum[lane];
#pragma unroll
        for (int off = 1; off < 32; off <<= 1) {
            int q = __shfl_up_sync(0xffffffff, w, off);
            if (lane >= off) w += q;
        }
        wsum[lane] = w;
    }
    __syncthreads();
    int excl = inc - sum + (wid > 0 ? wsum[wid - 1] : 0);
    int run = excl;
#pragma unroll
    for (int k = 0; k < 4; k++) {
        int idx = base + t * 4 + k;
        if (idx < n) g_rowptr[idx] = run;
        run += v[k];
    }
    // publish tile total, grab ticket; last block finalizes prefixes
    if (t == 1023) {
        g_bsum[blockIdx.x] = excl + sum;
        __threadfence();
        int old = atomicAdd(&g_ticket, 1);
        is_last = (old == (int)gridDim.x - 1) ? 1 : 0;
    }
    __syncthreads();
    if (is_last && wid == 0) {
        __threadfence();
        int nb = (int)gridDim.x;
        int vv = (lane < nb) ? g_bsum[lane] : 0;
        int ii = vv;
#pragma unroll
        for (int off = 1; off < 32; off <<= 1) {
            int q = __shfl_up_sync(0xffffffff, ii, off);
            if (lane >= off) ii += q;
        }
        if (lane < nb) g_bsum[lane] = ii - vv;   // exclusive tile prefix
        if (lane == 0) g_ticket = 0;             // restore invariant for next replay
    }
}

// 3) scatter normalized (col, weight); countdown cursor leaves g_fill at 0
__global__ void k_scatter(const int* __restrict__ row, const int* __restrict__ col,
                          const float* __restrict__ vals, int e) {
    int i = blockIdx.x * blockDim.x + threadIdx.x;
    if (i < e) {
        int r = __ldg(&row[i]), c = __ldg(&col[i]);
        int base = g_rowptr[r] + __ldg(&g_bsum[r >> 12]);
        int pos = base + atomicSub(&g_fill[r], 1) - 1;
        float w = __ldg(&vals[i]) * g_dinv[r] * g_dinv[c];
        g_ecw[pos] = make_int2(c, __float_as_int(w));
    }
}

// ---------------- weight repack + node_features fp16 conversion (fused) ----------------
__global__ void k_prep(const float* __restrict__ Win, const float* __restrict__ Wc,
                       const float* __restrict__ nf, int L, int wtot, int cnt4) {
    int t = blockIdx.x * blockDim.x + threadIdx.x;
    if (t < wtot) {
        const float* W;
        int idx;
        if (t < 1536) { W = Win; idx = t; }
        else {
            int l = (t - 1536) >> 12;
            idx = (t - 1536) & 4095;
            W = Wc + (size_t)l * ND * ND;
        }
        int kc   = idx >> 9;
        int rest = idx & 511;
        int nt   = rest >> 5;
        int lane = rest & 31;
        int n  = nt * 8 + (lane >> 2);
        int k0 = kc * 16 + (lane & 3) * 2;
        uint2 p;
        p.x = pack_h2(W[(size_t)k0 * ND + n],       W[(size_t)(k0 + 1) * ND + n]);
        p.y = pack_h2(W[(size_t)(k0 + 8) * ND + n], W[(size_t)(k0 + 9) * ND + n]);
        g_wpack[t] = p;
    } else {
        int i = t - wtot;
        if (i < cnt4) {
            float4 v = ((const float4*)nf)[i];
            uint2 p;
            p.x = pack_h2(v.x, v.y);
            p.y = pack_h2(v.z, v.w);
            ((uint2*)g_nfh)[i] = p;
        }
    }
}

// ---------------- tensor-core GEMM ----------------
// Block: 64 rows x 128 cols, 256 threads (8 warps). Warp: rg = w/2, col-half h = w%2.
// MODE 0: out = relu(acc + bias) -> Xout fp32 AND g_xh fp16 (input projection)
// MODE 1: out = acc -> g_y fp16 (layer pre-aggregation)
template<int KC, int MODE, int ASEL>
__global__ void __launch_bounds__(256)
k_mma(int wofs, const float* __restrict__ bias, float* __restrict__ Xout, int n) {
    const int AS = KC * 16;
    const __half* A = (ASEL == 0) ? g_nfh : g_xh;
    int tid = threadIdx.x;
    int warp = tid >> 5, lane = tid & 31;
    int rg = warp >> 1, h = warp & 1;
    int g = lane >> 2, tq = lane & 3;
    int row0 = blockIdx.x * 64 + rg * 16;

    float4 acc[8];
#pragma unroll
    for (int nt = 0; nt < 8; nt++) acc[nt] = make_float4(0.f, 0.f, 0.f, 0.f);

    const __half* ar0 = A + (size_t)(row0 + g) * AS;
    const __half* ar8 = A + (size_t)(row0 + g + 8) * AS;
    const uint2* wp = g_wpack + wofs + h * 256 + lane;

#pragma unroll
    for (int kc = 0; kc < KC; kc++) {
        int k0 = kc * 16 + tq * 2;
        unsigned a0 = *(const unsigned*)(ar0 + k0);
        unsigned a1 = *(const unsigned*)(ar8 + k0);
        unsigned a2 = *(const unsigned*)(ar0 + k0 + 8);
        unsigned a3 = *(const unsigned*)(ar8 + k0 + 8);
        const uint2* w = wp + kc * 512;
#pragma unroll
        for (int nt = 0; nt < 8; nt++) {
            uint2 b = __ldg(&w[nt * 32]);
            mma16816(acc[nt], a0, a1, a2, a3, b.x, b.y);
        }
    }

    int r0 = row0 + g;
    int r1 = row0 + g + 8;
    bool ok0 = r0 < n, ok1 = r1 < n;
    int colb = h * 64 + tq * 2;

    if (MODE == 1) {
        __half* y0 = g_y + (size_t)r0 * ND + colb;
        __half* y1 = g_y + (size_t)r1 * ND + colb;
#pragma unroll
        for (int nt = 0; nt < 8; nt++) {
            unsigned h01 = pack_h2(acc[nt].x, acc[nt].y);
            unsigned h23 = pack_h2(acc[nt].z, acc[nt].w);
            if (ok0) *(unsigned*)(y0 + nt * 8) = h01;
            if (ok1) *(unsigned*)(y1 + nt * 8) = h23;
        }
    } else {
        __half* xh0 = g_xh + (size_t)r0 * ND + colb;
        __half* xh1 = g_xh + (size_t)r1 * ND + colb;
        float*  xo0 = Xout + (size_t)r0 * ND + colb;
        float*  xo1 = Xout + (size_t)r1 * ND + colb;
#pragma unroll
        for (int nt = 0; nt < 8; nt++) {
            float2 bb = __ldg(&((const float2*)bias)[h * 32 + nt * 4 + tq]);
            float v0 = fmaxf(acc[nt].x + bb.x, 0.f);
            float v1 = fmaxf(acc[nt].y + bb.y, 0.f);
            float v2 = fmaxf(acc[nt].z + bb.x, 0.f);
            float v3 = fmaxf(acc[nt].w + bb.y, 0.f);
            if (ok0) {
                *(float2*)(xo0 + nt * 8) = make_float2(v0, v1);
                *(unsigned*)(xh0 + nt * 8) = pack_h2(v0, v1);
            }
            if (ok1) {
                *(float2*)(xo1 + nt * 8) = make_float2(v2, v3);
                *(unsigned*)(xh1 + nt * 8) = pack_h2(v2, v3);
            }
        }
    }
}

// ---------------- SpMM (fp16 gather) + bias + ReLU + residual, fused ----------------
// x[w,:] += relu( sum_j ew[j]*y[col[j],:] + dinv[w]^2*y[w,:] + b )
// rowptr is tile-local; absolute offsets via g_bsum exclusive tile prefixes.
__global__ void k_spmm_fused(float* __restrict__ x, const float* __restrict__ b, int n,
                             int etot, int write_xh) {
    int gt = blockIdx.x * blockDim.x + threadIdx.x;
    int w = gt >> 5;
    int lane = gt & 31;
    if (w >= n) return;
    const uint2* y2 = (const uint2*)g_y;        // 4 halfs per lane
    float di = g_dinv[w];
    float s = di * di;                          // self-loop weight
    float4 v = h4_to_f4(__ldg(&y2[(size_t)w * 32 + lane]));
    float4 acc = make_float4(s * v.x, s * v.y, s * v.z, s * v.w);
    int jb = g_rowptr[w] + __ldg(&g_bsum[w >> 12]);
    int je = (w + 1 == n) ? etot : (g_rowptr[w + 1] + __ldg(&g_bsum[(w + 1) >> 12]));
    int j = jb;
    for (; j + 8 <= je; j += 8) {
        int2 e[8];
        uint2 u[8];
#pragma unroll
        for (int q = 0; q < 8; q++) e[q] = __ldg(&g_ecw[j + q]);
#pragma unroll
        for (int q = 0; q < 8; q++) u[q] = __ldg(&y2[(size_t)e[q].x * 32 + lane]);
#pragma unroll
        for (int q = 0; q < 8; q++) fma4(acc, __int_as_float(e[q].y), h4_to_f4(u[q]));
    }
    if (j + 4 <= je) {
        int2 e[4];
        uint2 u[4];
#pragma unroll
        for (int q = 0; q < 4; q++) e[q] = __ldg(&g_ecw[j + q]);
#pragma unroll
        for (int q = 0; q < 4; q++) u[q] = __ldg(&y2[(size_t)e[q].x * 32 + lane]);
#pragma unroll
        for (int q = 0; q < 4; q++) fma4(acc, __int_as_float(e[q].y), h4_to_f4(u[q]));
        j += 4;
    }
    for (; j < je; j++) {
        int2 e = __ldg(&g_ecw[j]);
        fma4(acc, __int_as_float(e.y), h4_to_f4(__ldg(&y2[(size_t)e.x * 32 + lane])));
    }
    float4 bb = __ldg(&((const float4*)b)[lane]);
    float4* x4 = (float4*)x;
    float4 xv = x4[(size_t)w * 32 + lane];
    xv.x += fmaxf(acc.x + bb.x, 0.f);
    xv.y += fmaxf(acc.y + bb.y, 0.f);
    xv.z += fmaxf(acc.z + bb.z, 0.f);
    xv.w += fmaxf(acc.w + bb.w, 0.f);
    x4[(size_t)w * 32 + lane] = xv;
    if (write_xh) {
        uint2 p;
        p.x = pack_h2(xv.x, xv.y);
        p.y = pack_h2(xv.z, xv.w);
        ((uint2*)g_xh)[(size_t)w * 32 + lane] = p;
    }
}

// ---------------- launch ----------------
extern "C" void kernel_launch(void* const* d_in, const int* in_sizes, int n_in,
                              void* d_out, int out_size) {
    const float* nf    = (const float*)d_in[0];   // [N,48]
    const int*   erow  = (const int*)d_in[1];     // [E]
    const int*   ecol  = (const int*)d_in[2];     // [E]
    const float* evals = (const float*)d_in[3];   // [E]
    const float* Win   = (const float*)d_in[4];   // [48,128]
    const float* bin   = (const float*)d_in[5];   // [128]
    const float* Wc    = (const float*)d_in[6];   // [L,128,128]
    const float* bc    = (const float*)d_in[7];   // [L,128]

    int N = in_sizes[0] / INDIM;
    int E = in_sizes[1];
    int L = in_sizes[6] / (ND * ND);
    if (N > NMAX) N = NMAX;
    if (E > EMAX) E = EMAX;
    if (L > 3) L = 3;
    if (L < 1) L = 1;

    float* x = (float*)d_out;

    int spmm_blocks = (N * 32 + 255) / 256;
    int gblocks = (N + 63) / 64;
    int nb = (N + 4095) / 4096;
    int wtot = 1536 + L * 4096;
    int cnt4 = N * INDIM / 4;

    // Fork a secondary stream for the dense prologue (prep + input proj + layer-0 y),
    // which is independent of the CSR build. Host-side objects only (no device alloc).
    cudaStream_t s2 = 0;
    cudaEvent_t evFork = 0, evJoin = 0;
    bool forked = false;
    if (cudaStreamCreateWithFlags(&s2, cudaStreamNonBlocking) == cudaSuccess) {
        if (cudaEventCreateWithFlags(&evFork, cudaEventDisableTiming) == cudaSuccess &&
            cudaEventCreateWithFlags(&evJoin, cudaEventDisableTiming) == cudaSuccess) {
            forked = true;
        }
    }

    if (forked) {
        cudaEventRecord(evFork, 0);
        cudaStreamWaitEvent(s2, evFork, 0);
    }
    cudaStream_t sb = forked ? s2 : 0;   // dense branch stream

    // dense branch: wpack/nfh -> input projection -> layer-0 y = x @ Wc[0]
    k_prep<<<(wtot + cnt4 + 255) / 256, 256, 0, sb>>>(Win, Wc, nf, L, wtot, cnt4);
    k_mma<3, 0, 0><<<gblocks, 256, 0, sb>>>(0, bin, x, N);
    k_mma<8, 1, 1><<<gblocks, 256, 0, sb>>>(1536, nullptr, nullptr, N);

    // CSR branch (default stream): rebuild graph structure + normalization
    k_edge_deg<<<(E + 255) / 256, 256>>>(erow, evals, E);
    k_scanA<<<nb, 1024>>>(N);                 // also finalizes tile prefixes (last block)
    k_scatter<<<(E + 255) / 256, 256>>>(erow, ecol, evals, E);

    if (forked) {
        cudaEventRecord(evJoin, s2);
        cudaStreamWaitEvent(0, evJoin, 0);
    }

    // layer 0 aggregation, then remaining layers
    k_spmm_fused<<<spmm_blocks, 256>>>(x, bc, N, E, L > 1);
    for (int l = 1; l < L; l++) {
        k_mma<8, 1, 1><<<gblocks, 256>>>(1536 + l * 4096, nullptr, nullptr, N);
        k_spmm_fused<<<spmm_blocks, 256>>>(x, bc + (size_t)l * ND, N, E, l != L - 1);
    }
}